// round 12
// baseline (speedup 1.0000x reference)
#include <cuda_runtime.h>
#include <math.h>

// Problem constants
#define SS        26
#define CC        80
#define CELLS     676        // 26*26
#define NB        32
#define BIMG      256
#define OBJCELLS  2028       // 3*676
#define NWORDS    (OBJCELLS/4)   // 507 float4 words
#define NCH       255        // 3*(5+80)
#define DIV       16.0f      // 416/26
#define INV_IMG   (1.0f/416.0f)
#define NTHR      128
#define NSLICE    4
#define GRID      (BIMG*NSLICE)   // 1024
#define WPS       127             // noobj float4 words per slice (last gets 126)

__constant__ float c_anchor[18] = {
    10.f,13.f, 16.f,30.f, 33.f,23.f, 30.f,61.f, 62.f,45.f,
    59.f,119.f, 116.f,90.f, 156.f,198.f, 373.f,326.f
};

__device__ float g_partial[GRID];
__device__ unsigned int g_done_count = 0;

// L2 evict_last via cache-policy register
__device__ __forceinline__ unsigned long long mk_policy() {
    unsigned long long pol;
    asm volatile("createpolicy.fractional.L2::evict_last.b64 %0, 1.0;" : "=l"(pol));
    return pol;
}
__device__ __forceinline__ float ldg_el(const float* p, unsigned long long pol) {
    float v;
    asm volatile("ld.global.nc.L2::cache_hint.f32 %0, [%1], %2;"
                 : "=f"(v) : "l"(p), "l"(pol));
    return v;
}
__device__ __forceinline__ float4 ldg_el4(const float* p, unsigned long long pol) {
    float4 v;
    asm volatile("ld.global.nc.L2::cache_hint.v4.f32 {%0,%1,%2,%3}, [%4], %5;"
                 : "=f"(v.x), "=f"(v.y), "=f"(v.z), "=f"(v.w) : "l"(p), "l"(pol));
    return v;
}

__global__ void __launch_bounds__(NTHR)
yolo_transposed_kernel(const float* __restrict__ bx,
                       const float* __restrict__ bbox,
                       const int*   __restrict__ bidx,
                       float* __restrict__ out)
{
    const int blk  = blockIdx.x;
    const int b    = blk >> 2;       // image
    const int s    = blk & 3;        // slice
    const int tid  = threadIdx.x;
    const int warp = tid >> 5;       // 4 warps
    const int lane = tid & 31;
    const float* __restrict__ x = bx + (size_t)b * NCH * CELLS;
    const unsigned long long pol = mk_policy();

    __shared__ float sredA[4];
    __shared__ float sredN[4];
    __shared__ int   s_cnt;
    __shared__ int   s_last;

    // ---- Per-LANE box geometry: lane = box index (coalesced bbox reads) ----
    const float* bp = bbox + ((size_t)b * NB + lane) * 5;
    float cls = bp[0], cx = bp[1], cy = bp[2];
    int nidx = bidx[b * NB + lane];
    int base = (nidx - 3) * 85;
    int ix = (int)(cx / DIV);
    int iy = (int)(cy / DIV);
    int o  = ix * SS + iy;
    int cls_i = (int)cls;

    // Per-box pointer for my lane's box
    const float* p = x + (size_t)base * CELLS + o;

    // This warp's 5 label channels: warp-uniform channel, lane = box
    // -> boxes with the same anchor share a 2704B row => line sharing (~25 wf vs 32)
    const int ch0 = s * 20 + warp * 5;

    const bool w0    = (warp == 0);
    const bool coord = w0 && (s == 0);

    // ---- Issue ALL gathers up front, fully overlapped ----
    float v0 = ldg_el(p + (size_t)(5 + ch0 + 0) * CELLS, pol);
    float v1 = ldg_el(p + (size_t)(5 + ch0 + 1) * CELLS, pol);
    float v2 = ldg_el(p + (size_t)(5 + ch0 + 2) * CELLS, pol);
    float v3 = ldg_el(p + (size_t)(5 + ch0 + 3) * CELLS, pol);
    float v4 = ldg_el(p + (size_t)(5 + ch0 + 4) * CELLS, pol);

    // Warp 0 (every slice): obj value for dedup subtraction
    float ov = 0.0f;
    if (w0) ov = ldg_el(p + 0 * CELLS, pol);

    // Slice 0 warp 0: remaining head channels + w/h (each lane = one full box)
    float rax = 0.f, ray = 0.f, t3 = 0.f, t4 = 0.f, bw = 0.f, bh = 0.f;
    if (coord) {
        rax = ldg_el(p + 1 * CELLS, pol);
        ray = ldg_el(p + 2 * CELLS, pol);
        t3  = ldg_el(p + 3 * CELLS, pol);
        t4  = ldg_el(p + 4 * CELLS, pol);
        bw  = bp[3];
        bh  = bp[4];
    }

    float4 nv = make_float4(0.f, 0.f, 0.f, 0.f);
    const int j4 = s * WPS + tid;
    const bool has_no = (tid < WPS) && (j4 < NWORDS);
    if (has_no) {
        int r    = j4 / (CELLS / 4);
        int rem4 = j4 - r * (CELLS / 4);
        nv = ldg_el4(x + (size_t)(r * 85) * CELLS + rem4 * 4, pol);
    }

    // ---- Label MSE: my lane's box, 5 warp-uniform channels ----
    float acc;
    {
        float h0 = (ch0 + 0 == cls_i) ? 1.0f : 0.0f;
        float h1 = (ch0 + 1 == cls_i) ? 1.0f : 0.0f;
        float h2 = (ch0 + 2 == cls_i) ? 1.0f : 0.0f;
        float h3 = (ch0 + 3 == cls_i) ? 1.0f : 0.0f;
        float h4 = (ch0 + 4 == cls_i) ? 1.0f : 0.0f;
        float d0 = v0 - h0, d1 = v1 - h1, d2 = v2 - h2, d3 = v3 - h3, d4 = v4 - h4;
        acc = (d0*d0 + d1*d1 + d2*d2 + d3*d3 + d4*d4) * (1.0f / (NB * CC));
    }

    // ---- Warp 0: per-image dedup via match_any; noobj subtraction term ----
    float no = nv.x * nv.x + nv.y * nv.y + nv.z * nv.z + nv.w * nv.w;
    int n_uniq = 0;
    if (w0) {
        int cell = (nidx - 3) * CELLS + o;
        unsigned int match = __match_any_sync(0xFFFFFFFFu, cell);
        bool is_uniq = (lane == (__ffs(match) - 1));
        n_uniq = __popc(__ballot_sync(0xFFFFFFFFu, is_uniq));
        // each of 4 slices subtracts identical total -> x0.25 so the sum is 1x
        if (is_uniq) no -= 0.25f * ov * ov;
    }

    // ---- Slice 0 warp 0: coord/obj loss, one full box per lane ----
    if (coord) {
        float ax = (cx - (float)ix * DIV) / DIV;
        float ay = (cy - (float)iy * DIV) / DIV;

        float sig3 = 1.0f / (1.0f + __expf(-t3));
        float sig4 = 1.0f / (1.0f + __expf(-t4));
        float rw = c_anchor[nidx * 2 + 0] * __expf(4.0f * sig3 - 2.0f);
        float rh = c_anchor[nidx * 2 + 1] * __expf(4.0f * sig4 - 2.0f);

        float b1x0 = rax * DIV - rw * 0.5f, b1y0 = ray * DIV - rh * 0.5f;
        float b1x1 = rax * DIV + rw * 0.5f, b1y1 = ray * DIV + rh * 0.5f;
        float b2x0 = ax  * DIV - bw * 0.5f, b2y0 = ay  * DIV - bh * 0.5f;
        float b2x1 = ax  * DIV + bw * 0.5f, b2y1 = ay  * DIV + bh * 0.5f;

        float A  = (b1x1 - b1x0 + 1.0f) * (b1y1 - b1y0 + 1.0f);
        float Bt = (b2x1 - b2x0 + 1.0f) * (b2y1 - b2y0 + 1.0f);
        float CM = (fminf(b1x1, b2x1) - fmaxf(b1x0, b2x0) + 1.0f)
                 * (fminf(b1y1, b2y1) - fmaxf(b1y0, b2y0) + 1.0f);
        float iou = CM / (A + Bt - CM);
        iou = (iou < 0.0f) ? 0.0f : iou;

        float e0 = ov - iou;          // ov == obj_pred for my box
        float e1 = rax - ax;
        float e2 = ray - ay;
        float e3 = (rw - bw) * INV_IMG;
        float e4 = (rh - bh) * INV_IMG;

        acc += 5.0f * (e0*e0 + e1*e1 + e2*e2 + e3*e3 + e4*e4) * (1.0f / NB);
    }

    // ---- Deterministic shuffle reduction over 4 warps ----
    #pragma unroll
    for (int off = 16; off > 0; off >>= 1) {
        acc += __shfl_down_sync(0xFFFFFFFFu, acc, off);
        no  += __shfl_down_sync(0xFFFFFFFFu, no,  off);
    }
    if (lane == 0) {
        sredA[warp] = acc;
        sredN[warp] = no;
        if (warp == 0) s_cnt = n_uniq;   // uniform across warp 0
    }
    __syncthreads();

    if (tid == 0) {
        float A  = sredA[0] + sredA[1] + sredA[2] + sredA[3];
        float Nn = sredN[0] + sredN[1] + sredN[2] + sredN[3];
        float cnt = (float)(OBJCELLS - s_cnt);
        g_partial[blk] = A + 0.5f * Nn / cnt;
        __threadfence();
        unsigned int old = atomicAdd(&g_done_count, 1u);
        s_last = (old == GRID - 1) ? 1 : 0;
    }
    __syncthreads();

    // ---- Last block standing: deterministic fixed-order reduction of 1024 partials ----
    if (s_last) {
        float v = 0.0f;
        #pragma unroll
        for (int k = 0; k < GRID / NTHR; k++)
            v += g_partial[tid + k * NTHR];
        #pragma unroll
        for (int off = 16; off > 0; off >>= 1)
            v += __shfl_down_sync(0xFFFFFFFFu, v, off);
        if (lane == 0) sredA[warp] = v;
        __syncthreads();
        if (tid == 0) {
            out[0] = sredA[0] + sredA[1] + sredA[2] + sredA[3];
            atomicExch(&g_done_count, 0u);   // reset for next graph replay
        }
    }
}

extern "C" void kernel_launch(void* const* d_in, const int* in_sizes, int n_in,
                              void* d_out, int out_size)
{
    const float* bx   = (const float*)d_in[0];
    const float* bbox = (const float*)d_in[1];
    const int*   bidx = (const int*)d_in[2];
    float* out = (float*)d_out;

    yolo_transposed_kernel<<<GRID, NTHR>>>(bx, bbox, bidx, out);
}